// round 3
// baseline (speedup 1.0000x reference)
#include <cuda_runtime.h>

#define B_ 16
#define N_ 1024
#define F_ 256
#define H_ 4
#define D_ 64
#define BH_ (B_*H_)
#define NEG_SLOPE 0.2f

// Scratch (allocation-free rule: __device__ globals)
__device__ float g_Wh[(size_t)BH_ * N_ * D_];   // [b*H+h][n][d], 16 MB
__device__ float g_s1[BH_ * N_];
__device__ float g_s2[BH_ * N_];
__device__ float g_m2[BH_];                     // max over masked j of s2

// ---------------------------------------------------------------------------
// Kernel A: Wh = h @ W^T, scattered directly into [bh][n][d] layout.
// grid (M/64=256, OUT_F/64=4 == head index), block 256. BM=BN=64, BK=16.
// ---------------------------------------------------------------------------
__global__ __launch_bounds__(256) void k_gemm(const float* __restrict__ h,
                                              const float* __restrict__ W) {
    __shared__ float As[16][68];   // [k][m], padded: row stride 272B (16B-aligned)
    __shared__ float Bs[16][68];   // [k][o]
    const int bm  = blockIdx.x;
    const int hy  = blockIdx.y;          // head index (64-col tile == one head)
    const int tid = threadIdx.x;
    const int tx  = tid & 15, ty = tid >> 4;
    const int lr  = tid >> 2, lc = tid & 3;

    const float* ha = h + (size_t)(bm * 64 + lr) * F_;
    const float* wa = W + (size_t)(hy * 64 + lr) * F_;

    float acc[4][4];
#pragma unroll
    for (int i = 0; i < 4; i++)
#pragma unroll
        for (int j = 0; j < 4; j++) acc[i][j] = 0.f;

    for (int kt = 0; kt < F_; kt += 16) {
        float4 av = *(const float4*)(ha + kt + lc * 4);
        float4 bv = *(const float4*)(wa + kt + lc * 4);
        As[lc*4+0][lr] = av.x; As[lc*4+1][lr] = av.y;
        As[lc*4+2][lr] = av.z; As[lc*4+3][lr] = av.w;
        Bs[lc*4+0][lr] = bv.x; Bs[lc*4+1][lr] = bv.y;
        Bs[lc*4+2][lr] = bv.z; Bs[lc*4+3][lr] = bv.w;
        __syncthreads();
#pragma unroll
        for (int k = 0; k < 16; k++) {
            float4 a4 = *(const float4*)&As[k][ty * 4];
            float4 b4 = *(const float4*)&Bs[k][tx * 4];
            float ar[4] = {a4.x, a4.y, a4.z, a4.w};
            float br[4] = {b4.x, b4.y, b4.z, b4.w};
#pragma unroll
            for (int i = 0; i < 4; i++)
#pragma unroll
                for (int j = 0; j < 4; j++)
                    acc[i][j] = fmaf(ar[i], br[j], acc[i][j]);
        }
        __syncthreads();
    }

#pragma unroll
    for (int i = 0; i < 4; i++) {
        int row = bm * 64 + ty * 4 + i;        // global (b,n) row
        int b = row >> 10, n = row & 1023;
        float4 st = make_float4(acc[i][0], acc[i][1], acc[i][2], acc[i][3]);
        *(float4*)(g_Wh + ((size_t)(b * H_ + hy) * N_ + n) * D_ + tx * 4) = st;
    }
}

// ---------------------------------------------------------------------------
// Kernel B: s1,s2 per (bh,n) + masked max of s2 per bh. grid 64, block 256.
// ---------------------------------------------------------------------------
__global__ __launch_bounds__(256) void k_scores(const int* __restrict__ mask,
                                                const float* __restrict__ a) {
    __shared__ float sa[128];
    __shared__ float red[256];
    const int bh = blockIdx.x, b = bh >> 2, tid = threadIdx.x;
    if (tid < 128) sa[tid] = a[tid];
    __syncthreads();

    float lmax = -3.0e38f;
    for (int n = tid; n < N_; n += 256) {
        const float4* row = (const float4*)(g_Wh + ((size_t)bh * N_ + n) * D_);
        float s1 = 0.f, s2 = 0.f;
#pragma unroll
        for (int q = 0; q < 16; q++) {
            float4 v = row[q];
            s1 += v.x * sa[q*4+0] + v.y * sa[q*4+1] + v.z * sa[q*4+2] + v.w * sa[q*4+3];
            s2 += v.x * sa[64+q*4+0] + v.y * sa[64+q*4+1] + v.z * sa[64+q*4+2] + v.w * sa[64+q*4+3];
        }
        g_s1[bh * N_ + n] = s1;
        g_s2[bh * N_ + n] = s2;
        if (mask[b * N_ + n]) lmax = fmaxf(lmax, s2);
    }
    red[tid] = lmax;
    __syncthreads();
    for (int s = 128; s > 0; s >>= 1) {
        if (tid < s) red[tid] = fmaxf(red[tid], red[tid + s]);
        __syncthreads();
    }
    if (tid == 0) g_m2[bh] = red[0];
}

// ---------------------------------------------------------------------------
// Kernel C: h'[i,:] = softmax_j(f(s1_i+s2_j)) @ Wh.
// One thread per row i (lane-per-row => Wh smem reads are pure broadcast).
// Row max = f(s1_i + max_j s2_j) since leakyrelu is monotone.
// Accumulators packed f32x2 -> fma.rn.f32x2 (FFMA2, 2x fp32 throughput).
// grid (N/128=8, BH=64), block 128.
// ---------------------------------------------------------------------------
__global__ __launch_bounds__(128) void k_attn(const int* __restrict__ mask,
                                              float* __restrict__ out) {
    __shared__ float sWh[128 * 64];   // 32 KB j-tile of Wh
    __shared__ float sS[128];         // masked s2 tile
    const int bh = blockIdx.y, b = bh >> 2, hh = bh & 3;
    const int tid = threadIdx.x;
    const int i = blockIdx.x * 128 + tid;

    const float* WhB = g_Wh + (size_t)bh * N_ * D_;
    const float s1i = g_s1[bh * N_ + i];
    const float m2  = g_m2[bh];
    const float t0  = s1i + m2;
    const float rowmax = t0 >= 0.f ? t0 : NEG_SLOPE * t0;
    const int   mi = mask[b * N_ + i];

    unsigned long long acc[32];   // 64 fp32 accumulators as 32 x f32x2
#pragma unroll
    for (int q = 0; q < 32; q++) acc[q] = 0ull;
    float wsum = 0.f;

    for (int jt = 0; jt < N_; jt += 128) {
        const float4* src = (const float4*)(WhB + (size_t)jt * D_);
        float4* dst = (float4*)sWh;
#pragma unroll
        for (int q = 0; q < 16; q++) dst[q * 128 + tid] = src[q * 128 + tid];
        {
            int j = jt + tid;
            sS[tid] = mask[b * N_ + j] ? g_s2[bh * N_ + j] : -1.0e30f;
        }
        __syncthreads();

#pragma unroll 2
        for (int jj = 0; jj < 128; jj++) {
            float t  = s1i + sS[jj];
            float fe = t >= 0.f ? t : NEG_SLOPE * t;
            float w  = __expf(fe - rowmax);
            wsum += w;
            unsigned long long wp;
            asm("mov.b64 %0, {%1, %1};" : "=l"(wp) : "r"(__float_as_uint(w)));
            const ulonglong2* vp = (const ulonglong2*)(sWh + jj * 64);
#pragma unroll
            for (int q = 0; q < 16; q++) {
                ulonglong2 v = vp[q];   // broadcast LDS.128 (all lanes same addr)
                asm("fma.rn.f32x2 %0, %1, %2, %0;" : "+l"(acc[2*q+0]) : "l"(wp), "l"(v.x));
                asm("fma.rn.f32x2 %0, %1, %2, %0;" : "+l"(acc[2*q+1]) : "l"(wp), "l"(v.y));
            }
        }
        __syncthreads();
    }

    const bool good = mi && (m2 > -1.0e29f) && (wsum > 0.f);
    float4* op = (float4*)(out + ((size_t)(b * N_ + i)) * (H_ * D_) + hh * D_);
    if (good) {
        const float inv = 1.f / wsum;
#pragma unroll
        for (int q = 0; q < 16; q++) {
            unsigned long long a0 = acc[2*q+0], a1 = acc[2*q+1];
            float4 o;
            o.x = __uint_as_float((unsigned)(a0      )) * inv;
            o.y = __uint_as_float((unsigned)(a0 >> 32)) * inv;
            o.z = __uint_as_float((unsigned)(a1      )) * inv;
            o.w = __uint_as_float((unsigned)(a1 >> 32)) * inv;
            op[q] = o;
        }
    } else {
        float4 z = make_float4(0.f, 0.f, 0.f, 0.f);
#pragma unroll
        for (int q = 0; q < 16; q++) op[q] = z;
    }
}

// ---------------------------------------------------------------------------
extern "C" void kernel_launch(void* const* d_in, const int* in_sizes, int n_in,
                              void* d_out, int out_size) {
    const float* h    = (const float*)d_in[0];   // [16,1024,256] f32
    const int*   mask = (const int*)  d_in[1];   // [16,1024] i32
    const float* W    = (const float*)d_in[2];   // [256,256] f32
    const float* a    = (const float*)d_in[3];   // [128,1] f32
    float* out = (float*)d_out;                  // [16,1024,256] f32

    k_gemm  <<<dim3(256, 4), 256>>>(h, W);
    k_scores<<<64, 256>>>(mask, a);
    k_attn  <<<dim3(N_ / 128, BH_), 128>>>(mask, out);
}

// round 5
// speedup vs baseline: 2.2499x; 2.2499x over previous
#include <cuda_runtime.h>

#define B_ 16
#define N_ 1024
#define F_ 256
#define H_ 4
#define D_ 64
#define BH_ (B_*H_)
#define NEG_SLOPE 0.2f
#define LOG2E 1.4426950408889634f

// Scratch (allocation-free rule: __device__ globals)
__device__ float g_Wh[(size_t)BH_ * N_ * D_];   // [b*H+h][n][d], 16 MB
__device__ float g_s1[BH_ * N_];
__device__ float g_s2[BH_ * N_];
__device__ float g_m2[BH_];                     // max over masked j of s2

// ---------------------------------------------------------------------------
// Kernel A: Wh = h @ W^T, scattered directly into [bh][n][d] layout.
// ---------------------------------------------------------------------------
__global__ __launch_bounds__(256) void k_gemm(const float* __restrict__ h,
                                              const float* __restrict__ W) {
    __shared__ float As[16][68];
    __shared__ float Bs[16][68];
    const int bm  = blockIdx.x;
    const int hy  = blockIdx.y;
    const int tid = threadIdx.x;
    const int tx  = tid & 15, ty = tid >> 4;
    const int lr  = tid >> 2, lc = tid & 3;

    const float* ha = h + (size_t)(bm * 64 + lr) * F_;
    const float* wa = W + (size_t)(hy * 64 + lr) * F_;

    float acc[4][4];
#pragma unroll
    for (int i = 0; i < 4; i++)
#pragma unroll
        for (int j = 0; j < 4; j++) acc[i][j] = 0.f;

    for (int kt = 0; kt < F_; kt += 16) {
        float4 av = *(const float4*)(ha + kt + lc * 4);
        float4 bv = *(const float4*)(wa + kt + lc * 4);
        As[lc*4+0][lr] = av.x; As[lc*4+1][lr] = av.y;
        As[lc*4+2][lr] = av.z; As[lc*4+3][lr] = av.w;
        Bs[lc*4+0][lr] = bv.x; Bs[lc*4+1][lr] = bv.y;
        Bs[lc*4+2][lr] = bv.z; Bs[lc*4+3][lr] = bv.w;
        __syncthreads();
#pragma unroll
        for (int k = 0; k < 16; k++) {
            float4 a4 = *(const float4*)&As[k][ty * 4];
            float4 b4 = *(const float4*)&Bs[k][tx * 4];
            float ar[4] = {a4.x, a4.y, a4.z, a4.w};
            float br[4] = {b4.x, b4.y, b4.z, b4.w};
#pragma unroll
            for (int i = 0; i < 4; i++)
#pragma unroll
                for (int j = 0; j < 4; j++)
                    acc[i][j] = fmaf(ar[i], br[j], acc[i][j]);
        }
        __syncthreads();
    }

#pragma unroll
    for (int i = 0; i < 4; i++) {
        int row = bm * 64 + ty * 4 + i;
        int b = row >> 10, n = row & 1023;
        float4 st = make_float4(acc[i][0], acc[i][1], acc[i][2], acc[i][3]);
        *(float4*)(g_Wh + ((size_t)(b * H_ + hy) * N_ + n) * D_ + tx * 4) = st;
    }
}

// ---------------------------------------------------------------------------
// Kernel B: s1,s2 per (bh,n) + masked max of s2 per bh. grid 64, block 256.
// ---------------------------------------------------------------------------
__global__ __launch_bounds__(256) void k_scores(const int* __restrict__ mask,
                                                const float* __restrict__ a) {
    __shared__ float sa[128];
    __shared__ float red[256];
    const int bh = blockIdx.x, b = bh >> 2, tid = threadIdx.x;
    if (tid < 128) sa[tid] = a[tid];
    __syncthreads();

    float lmax = -3.0e38f;
    for (int n = tid; n < N_; n += 256) {
        const float4* row = (const float4*)(g_Wh + ((size_t)bh * N_ + n) * D_);
        float s1 = 0.f, s2 = 0.f;
#pragma unroll
        for (int q = 0; q < 16; q++) {
            float4 v = row[q];
            s1 += v.x * sa[q*4+0] + v.y * sa[q*4+1] + v.z * sa[q*4+2] + v.w * sa[q*4+3];
            s2 += v.x * sa[64+q*4+0] + v.y * sa[64+q*4+1] + v.z * sa[64+q*4+2] + v.w * sa[64+q*4+3];
        }
        g_s1[bh * N_ + n] = s1;
        g_s2[bh * N_ + n] = s2;
        if (mask[b * N_ + n]) lmax = fmaxf(lmax, s2);
    }
    red[tid] = lmax;
    __syncthreads();
    for (int s = 128; s > 0; s >>= 1) {
        if (tid < s) red[tid] = fmaxf(red[tid], red[tid + s]);
        __syncthreads();
    }
    if (tid == 0) g_m2[bh] = red[0];
}

// ---------------------------------------------------------------------------
// Kernel C (tensor cores): h'[i,:] = softmax_j(f(s1_i+s2_j)) @ Wh.
// tf32 mma.m16n8k8, P computed on the fly in A-fragment layout.
// grid (N/256=4, BH=64), block 256 (8 warps). Warp w: i rows [w*16,w*16+16)
// and [128+w*16, ...). smem Wh tile: [128 j][stride 72] -> conflict-free B lds.
// ---------------------------------------------------------------------------
__device__ __forceinline__ float ex2f(float x) {
    float r; asm("ex2.approx.f32 %0, %1;" : "=f"(r) : "f"(x)); return r;
}
__device__ __forceinline__ unsigned cvt_tf32(float x) {
    unsigned r; asm("cvt.rna.tf32.f32 %0, %1;" : "=r"(r) : "f"(x)); return r;
}

__global__ __launch_bounds__(256) void k_attn_tc(const int* __restrict__ mask,
                                                 float* __restrict__ out) {
    __shared__ float sWh[128 * 72];   // 36 KB j-tile
    __shared__ float sS[128];
    const int bh = blockIdx.y, b = bh >> 2, hh = bh & 3;
    const int tid = threadIdx.x;
    const int warp = tid >> 5, lane = tid & 31;
    const int g  = lane >> 2;     // group id (n/row group)
    const int tg = lane & 3;      // thread-in-group (k col)
    const int ib = blockIdx.x * 256;

    const float m2 = g_m2[bh];
    const bool m2ok = (m2 > -1.0e29f);

    // 4 C-fragment rows owned by this thread: frag0 {g, g+8}, frag1 {+128}
    int r0 = ib + warp * 16 + g;
    int rr[4] = { r0, r0 + 8, r0 + 128, r0 + 136 };

    float s1v[4], rmL[4];
    int   mrow[4];
#pragma unroll
    for (int q = 0; q < 4; q++) {
        float s1 = g_s1[bh * N_ + rr[q]];
        float t0 = s1 + m2;
        float rm = fmaxf(t0, NEG_SLOPE * t0);    // leakyrelu (slope>0)
        s1v[q] = s1;
        rmL[q] = rm * LOG2E;
        mrow[q] = mask[b * N_ + rr[q]];
    }

    float acc[2][8][4];
#pragma unroll
    for (int f = 0; f < 2; f++)
#pragma unroll
        for (int nt = 0; nt < 8; nt++)
#pragma unroll
            for (int q = 0; q < 4; q++) acc[f][nt][q] = 0.f;
    float wsum[4] = {0.f, 0.f, 0.f, 0.f};

    for (int jt = 0; jt < N_; jt += 128) {
        // fill Wh tile: 128 rows x 64 f32, smem row stride 72
        {
            const float* src = g_Wh + ((size_t)bh * N_ + jt) * D_;
            int row = tid >> 1;
            int c0  = (tid & 1) * 32;
            const float4* s4 = (const float4*)(src + (size_t)row * D_ + c0);
            float4* d4 = (float4*)(sWh + row * 72 + c0);
#pragma unroll
            for (int q = 0; q < 8; q++) d4[q] = s4[q];
        }
        if (tid < 128) {
            int j = jt + tid;
            sS[tid] = mask[b * N_ + j] ? g_s2[bh * N_ + j] : -1.0e30f;
        }
        __syncthreads();

#pragma unroll 1
        for (int ks = 0; ks < 16; ks++) {
            const int j0 = ks * 8;
            const float s2a = sS[j0 + tg];       // k cols tg
            const float s2b = sS[j0 + 4 + tg];   // k cols tg+4

            // A fragments (P weights), computed in place
            unsigned af[2][4];
#pragma unroll
            for (int f = 0; f < 2; f++) {
                float sA = s1v[f*2+0], rA = rmL[f*2+0];
                float sB = s1v[f*2+1], rB = rmL[f*2+1];
                float t;
                t = sA + s2a; float w0 = ex2f(fmaf(fmaxf(t, NEG_SLOPE*t), LOG2E, -rA));
                t = sB + s2a; float w1 = ex2f(fmaf(fmaxf(t, NEG_SLOPE*t), LOG2E, -rB));
                t = sA + s2b; float w2 = ex2f(fmaf(fmaxf(t, NEG_SLOPE*t), LOG2E, -rA));
                t = sB + s2b; float w3 = ex2f(fmaf(fmaxf(t, NEG_SLOPE*t), LOG2E, -rB));
                wsum[f*2+0] += w0 + w2;
                wsum[f*2+1] += w1 + w3;
                af[f][0] = cvt_tf32(w0); af[f][1] = cvt_tf32(w1);
                af[f][2] = cvt_tf32(w2); af[f][3] = cvt_tf32(w3);
            }

            // B fragments: Wh[j0+tg(+4)][nt*8 + g]; banks (8j+c)%32 distinct
            const float* p0 = sWh + (j0 + tg) * 72 + g;
            const float* p1 = sWh + (j0 + 4 + tg) * 72 + g;
            unsigned bf[8][2];
#pragma unroll
            for (int nt = 0; nt < 8; nt++) {
                bf[nt][0] = cvt_tf32(p0[nt * 8]);
                bf[nt][1] = cvt_tf32(p1[nt * 8]);
            }

#pragma unroll
            for (int f = 0; f < 2; f++)
#pragma unroll
                for (int nt = 0; nt < 8; nt++) {
                    asm volatile(
                        "mma.sync.aligned.m16n8k8.row.col.f32.tf32.tf32.f32 "
                        "{%0,%1,%2,%3}, {%4,%5,%6,%7}, {%8,%9}, {%0,%1,%2,%3};"
                        : "+f"(acc[f][nt][0]), "+f"(acc[f][nt][1]),
                          "+f"(acc[f][nt][2]), "+f"(acc[f][nt][3])
                        : "r"(af[f][0]), "r"(af[f][1]), "r"(af[f][2]), "r"(af[f][3]),
                          "r"(bf[nt][0]), "r"(bf[nt][1]));
                }
        }
        __syncthreads();
    }

    // full row sums: reduce across the 4 lanes of each group
#pragma unroll
    for (int q = 0; q < 4; q++) {
        wsum[q] += __shfl_xor_sync(0xffffffffu, wsum[q], 1);
        wsum[q] += __shfl_xor_sync(0xffffffffu, wsum[q], 2);
    }

    // write out: C frag layout: reg (q&1)*2 + {0,1} at cols nt*8 + tg*2 {+1}
#pragma unroll
    for (int q = 0; q < 4; q++) {
        const bool good = mrow[q] && m2ok && (wsum[q] > 0.f);
        const float inv = 1.f / wsum[q];
        const int f = q >> 1;
        const int lohi = (q & 1) * 2;   // 0 for rows g, 2 for rows g+8
        float* op = out + ((size_t)(b * N_ + rr[q])) * (H_ * D_) + hh * D_ + tg * 2;
#pragma unroll
        for (int nt = 0; nt < 8; nt++) {
            float2 v;
            v.x = good ? acc[f][nt][lohi + 0] * inv : 0.f;
            v.y = good ? acc[f][nt][lohi + 1] * inv : 0.f;
            *(float2*)(op + nt * 8) = v;
        }
    }
}

// ---------------------------------------------------------------------------
extern "C" void kernel_launch(void* const* d_in, const int* in_sizes, int n_in,
                              void* d_out, int out_size) {
    const float* h    = (const float*)d_in[0];   // [16,1024,256] f32
    const int*   mask = (const int*)  d_in[1];   // [16,1024] i32
    const float* W    = (const float*)d_in[2];   // [256,256] f32
    const float* a    = (const float*)d_in[3];   // [128,1] f32
    float* out = (float*)d_out;                  // [16,1024,256] f32

    k_gemm   <<<dim3(256, 4), 256>>>(h, W);
    k_scores <<<64, 256>>>(mask, a);
    k_attn_tc<<<dim3(N_ / 256, BH_), 256>>>(mask, out);
}

// round 9
// speedup vs baseline: 2.4598x; 1.0933x over previous
#include <cuda_runtime.h>
#include <cuda_bf16.h>

#define B_ 16
#define N_ 1024
#define F_ 256
#define H_ 4
#define D_ 64
#define BH_ (B_*H_)
#define NEG_SLOPE 0.2f
#define LOG2E 1.4426950408889634f

// Scratch (allocation-free rule: __device__ globals)
__device__ float g_Wh[(size_t)BH_ * N_ * D_];   // [b*H+h][n][d], 16 MB
__device__ float g_s1[BH_ * N_];
__device__ float g_s2[BH_ * N_];
__device__ float g_m2[BH_];                     // max over masked j of s2

__device__ __forceinline__ float ex2f(float x) {
    float r; asm("ex2.approx.f32 %0, %1;" : "=f"(r) : "f"(x)); return r;
}
__device__ __forceinline__ unsigned cvt_tf32(float x) {
    unsigned r; asm("cvt.rna.tf32.f32 %0, %1;" : "=r"(r) : "f"(x)); return r;
}

#define MMA_BF16(d, a, b) asm volatile( \
    "mma.sync.aligned.m16n8k16.row.col.f32.bf16.bf16.f32 " \
    "{%0,%1,%2,%3}, {%4,%5,%6,%7}, {%8,%9}, {%0,%1,%2,%3};" \
    : "+f"((d)[0]), "+f"((d)[1]), "+f"((d)[2]), "+f"((d)[3]) \
    : "r"((a)[0]), "r"((a)[1]), "r"((a)[2]), "r"((a)[3]), \
      "r"((b)[0]), "r"((b)[1]))

// ---------------------------------------------------------------------------
// Kernel A (tensor cores): Wh = h @ W^T, split-bf16 (hi+lo), 3-term MMA.
// grid (16384/128=128, H=4), block 256 = 8 warps (4 m x 2 n).
// Block tile M=128, N=64(head), K chunked by 32. Warp tile 32x32.
// smem bf16 row stride 40 -> conflict-free frag LDS ((20g+tg) mod 32 distinct).
// ---------------------------------------------------------------------------
#define APAD 40
__global__ __launch_bounds__(256) void k_gemm_tc(const float* __restrict__ h,
                                                 const float* __restrict__ W) {
    __shared__ __nv_bfloat16 sAh[128 * APAD];
    __shared__ __nv_bfloat16 sAl[128 * APAD];
    __shared__ __nv_bfloat16 sBh[64 * APAD];
    __shared__ __nv_bfloat16 sBl[64 * APAD];

    const int tid  = threadIdx.x;
    const int warp = tid >> 5, lane = tid & 31;
    const int g  = lane >> 2;       // fragment row group
    const int tg = lane & 3;        // thread in group
    const int wm = warp >> 1;       // 0..3
    const int wn = warp & 1;        // 0..1
    const int m0 = blockIdx.x * 128;
    const int head = blockIdx.y;

    float acc[2][4][4];
#pragma unroll
    for (int mf = 0; mf < 2; mf++)
#pragma unroll
        for (int nf = 0; nf < 4; nf++)
#pragma unroll
            for (int q = 0; q < 4; q++) acc[mf][nf][q] = 0.f;

    for (int kt = 0; kt < F_; kt += 32) {
        // ---- fill A (all 256 threads: 128 rows x 2 k-halves) ----
        {
            const int r  = tid >> 1;
            const int hf = (tid & 1) * 16;
            const float4* src = (const float4*)(h + (size_t)(m0 + r) * F_ + kt + hf);
            __nv_bfloat16* dh = sAh + r * APAD + hf;
            __nv_bfloat16* dl = sAl + r * APAD + hf;
#pragma unroll
            for (int q = 0; q < 4; q++) {
                float4 v = src[q];
                float f[4] = {v.x, v.y, v.z, v.w};
#pragma unroll
                for (int e = 0; e < 4; e++) {
                    __nv_bfloat16 hi = __float2bfloat16(f[e]);
                    __nv_bfloat16 lo = __float2bfloat16(f[e] - __bfloat162float(hi));
                    dh[q * 4 + e] = hi;
                    dl[q * 4 + e] = lo;
                }
            }
        }
        // ---- fill B (threads 0..127: 64 rows x 2 k-halves) ----
        if (tid < 128) {
            const int r  = tid >> 1;
            const int hf = (tid & 1) * 16;
            const float4* src = (const float4*)(W + (size_t)(head * 64 + r) * F_ + kt + hf);
            __nv_bfloat16* dh = sBh + r * APAD + hf;
            __nv_bfloat16* dl = sBl + r * APAD + hf;
#pragma unroll
            for (int q = 0; q < 4; q++) {
                float4 v = src[q];
                float f[4] = {v.x, v.y, v.z, v.w};
#pragma unroll
                for (int e = 0; e < 4; e++) {
                    __nv_bfloat16 hi = __float2bfloat16(f[e]);
                    __nv_bfloat16 lo = __float2bfloat16(f[e] - __bfloat162float(hi));
                    dh[q * 4 + e] = hi;
                    dl[q * 4 + e] = lo;
                }
            }
        }
        __syncthreads();

#pragma unroll
        for (int ks = 0; ks < 2; ks++) {
            const int kb = ks * 16 + 2 * tg;
            unsigned ah[2][4], al[2][4], bh[4][2], bl[4][2];
#pragma unroll
            for (int mf = 0; mf < 2; mf++) {
                const int base = (wm * 32 + mf * 16 + g) * APAD;
                ah[mf][0] = *(const unsigned*)&sAh[base + kb];
                ah[mf][1] = *(const unsigned*)&sAh[base + 8 * APAD + kb];
                ah[mf][2] = *(const unsigned*)&sAh[base + kb + 8];
                ah[mf][3] = *(const unsigned*)&sAh[base + 8 * APAD + kb + 8];
                al[mf][0] = *(const unsigned*)&sAl[base + kb];
                al[mf][1] = *(const unsigned*)&sAl[base + 8 * APAD + kb];
                al[mf][2] = *(const unsigned*)&sAl[base + kb + 8];
                al[mf][3] = *(const unsigned*)&sAl[base + 8 * APAD + kb + 8];
            }
#pragma unroll
            for (int nf = 0; nf < 4; nf++) {
                const int bb = (wn * 32 + nf * 8 + g) * APAD + kb;
                bh[nf][0] = *(const unsigned*)&sBh[bb];
                bh[nf][1] = *(const unsigned*)&sBh[bb + 8];
                bl[nf][0] = *(const unsigned*)&sBl[bb];
                bl[nf][1] = *(const unsigned*)&sBl[bb + 8];
            }
#pragma unroll
            for (int mf = 0; mf < 2; mf++)
#pragma unroll
                for (int nf = 0; nf < 4; nf++) {
                    MMA_BF16(acc[mf][nf], ah[mf], bh[nf]);
                    MMA_BF16(acc[mf][nf], al[mf], bh[nf]);
                    MMA_BF16(acc[mf][nf], ah[mf], bl[nf]);
                }
        }
        __syncthreads();
    }

    // scatter to g_Wh[bh][n][d]
#pragma unroll
    for (int mf = 0; mf < 2; mf++) {
        const int row0 = m0 + wm * 32 + mf * 16 + g;
        const int b = row0 >> 10, n = row0 & 1023;
        float* base = g_Wh + ((size_t)(b * H_ + head) * N_ + n) * D_;
#pragma unroll
        for (int nf = 0; nf < 4; nf++) {
            const int d = wn * 32 + nf * 8 + 2 * tg;
            *(float2*)(base + d)            = make_float2(acc[mf][nf][0], acc[mf][nf][1]);
            *(float2*)(base + 8 * D_ + d)   = make_float2(acc[mf][nf][2], acc[mf][nf][3]);
        }
    }
}

// ---------------------------------------------------------------------------
// Kernel B: s1,s2 per (bh,n) + masked max of s2 per bh. grid 64, block 256.
// ---------------------------------------------------------------------------
__global__ __launch_bounds__(256) void k_scores(const int* __restrict__ mask,
                                                const float* __restrict__ a) {
    __shared__ float sa[128];
    __shared__ float red[256];
    const int bh = blockIdx.x, b = bh >> 2, tid = threadIdx.x;
    if (tid < 128) sa[tid] = a[tid];
    __syncthreads();

    float lmax = -3.0e38f;
    for (int n = tid; n < N_; n += 256) {
        const float4* row = (const float4*)(g_Wh + ((size_t)bh * N_ + n) * D_);
        float s1 = 0.f, s2 = 0.f;
#pragma unroll
        for (int q = 0; q < 16; q++) {
            float4 v = row[q];
            s1 += v.x * sa[q*4+0] + v.y * sa[q*4+1] + v.z * sa[q*4+2] + v.w * sa[q*4+3];
            s2 += v.x * sa[64+q*4+0] + v.y * sa[64+q*4+1] + v.z * sa[64+q*4+2] + v.w * sa[64+q*4+3];
        }
        g_s1[bh * N_ + n] = s1;
        g_s2[bh * N_ + n] = s2;
        if (mask[b * N_ + n]) lmax = fmaxf(lmax, s2);
    }
    red[tid] = lmax;
    __syncthreads();
    for (int s = 128; s > 0; s >>= 1) {
        if (tid < s) red[tid] = fmaxf(red[tid], red[tid + s]);
        __syncthreads();
    }
    if (tid == 0) g_m2[bh] = red[0];
}

// ---------------------------------------------------------------------------
// Kernel C (tensor cores): h'[i,:] = softmax_j(f(s1_i+s2_j)) @ Wh.
// tf32 mma.m16n8k8; Wh tile pre-converted to tf32 bits at smem fill.
// grid (N/256=4, BH=64), block 256 (8 warps).
// ---------------------------------------------------------------------------
__global__ __launch_bounds__(256) void k_attn_tc(const int* __restrict__ mask,
                                                 float* __restrict__ out) {
    __shared__ unsigned sWh[128 * 72];   // 36 KB j-tile, tf32 bit patterns
    __shared__ float sS[128];
    const int bh = blockIdx.y, b = bh >> 2, hh = bh & 3;
    const int tid = threadIdx.x;
    const int warp = tid >> 5, lane = tid & 31;
    const int g  = lane >> 2;
    const int tg = lane & 3;
    const int ib = blockIdx.x * 256;

    const float m2 = g_m2[bh];
    const bool m2ok = (m2 > -1.0e29f);

    int r0 = ib + warp * 16 + g;
    int rr[4] = { r0, r0 + 8, r0 + 128, r0 + 136 };

    float s1v[4], rmL[4];
    int   mrow[4];
#pragma unroll
    for (int q = 0; q < 4; q++) {
        float s1 = g_s1[bh * N_ + rr[q]];
        float t0 = s1 + m2;
        float rm = fmaxf(t0, NEG_SLOPE * t0);    // leakyrelu (slope>0)
        s1v[q] = s1;
        rmL[q] = rm * LOG2E;
        mrow[q] = mask[b * N_ + rr[q]];
    }

    float acc[2][8][4];
#pragma unroll
    for (int f = 0; f < 2; f++)
#pragma unroll
        for (int nt = 0; nt < 8; nt++)
#pragma unroll
            for (int q = 0; q < 4; q++) acc[f][nt][q] = 0.f;
    float wsum[4] = {0.f, 0.f, 0.f, 0.f};

    for (int jt = 0; jt < N_; jt += 128) {
        // fill Wh tile: 128 rows x 64, converted to tf32 at fill time
        {
            const float* src = g_Wh + ((size_t)bh * N_ + jt) * D_;
            int row = tid >> 1;
            int c0  = (tid & 1) * 32;
            const float4* s4 = (const float4*)(src + (size_t)row * D_ + c0);
            uint4* d4 = (uint4*)(sWh + row * 72 + c0);
#pragma unroll
            for (int q = 0; q < 8; q++) {
                float4 v = s4[q];
                uint4 u;
                u.x = cvt_tf32(v.x); u.y = cvt_tf32(v.y);
                u.z = cvt_tf32(v.z); u.w = cvt_tf32(v.w);
                d4[q] = u;
            }
        }
        if (tid < 128) {
            int j = jt + tid;
            sS[tid] = mask[b * N_ + j] ? g_s2[bh * N_ + j] : -1.0e30f;
        }
        __syncthreads();

#pragma unroll 1
        for (int ks = 0; ks < 16; ks++) {
            const int j0 = ks * 8;
            const float s2a = sS[j0 + tg];
            const float s2b = sS[j0 + 4 + tg];

            // A fragments (P weights), computed in place
            unsigned af[2][4];
#pragma unroll
            for (int f = 0; f < 2; f++) {
                float sA = s1v[f*2+0], rA = rmL[f*2+0];
                float sB = s1v[f*2+1], rB = rmL[f*2+1];
                float t;
                t = sA + s2a; float w0 = ex2f(fmaf(fmaxf(t, NEG_SLOPE*t), LOG2E, -rA));
                t = sB + s2a; float w1 = ex2f(fmaf(fmaxf(t, NEG_SLOPE*t), LOG2E, -rB));
                t = sA + s2b; float w2 = ex2f(fmaf(fmaxf(t, NEG_SLOPE*t), LOG2E, -rA));
                t = sB + s2b; float w3 = ex2f(fmaf(fmaxf(t, NEG_SLOPE*t), LOG2E, -rB));
                wsum[f*2+0] += w0 + w2;
                wsum[f*2+1] += w1 + w3;
                af[f][0] = cvt_tf32(w0); af[f][1] = cvt_tf32(w1);
                af[f][2] = cvt_tf32(w2); af[f][3] = cvt_tf32(w3);
            }

            // B fragments: pre-converted tf32 bits, conflict-free
            const unsigned* p0 = sWh + (j0 + tg) * 72 + g;
            const unsigned* p1 = sWh + (j0 + 4 + tg) * 72 + g;
            unsigned bf[8][2];
#pragma unroll
            for (int nt = 0; nt < 8; nt++) {
                bf[nt][0] = p0[nt * 8];
                bf[nt][1] = p1[nt * 8];
            }

#pragma unroll
            for (int f = 0; f < 2; f++)
#pragma unroll
                for (int nt = 0; nt < 8; nt++) {
                    asm volatile(
                        "mma.sync.aligned.m16n8k8.row.col.f32.tf32.tf32.f32 "
                        "{%0,%1,%2,%3}, {%4,%5,%6,%7}, {%8,%9}, {%0,%1,%2,%3};"
                        : "+f"(acc[f][nt][0]), "+f"(acc[f][nt][1]),
                          "+f"(acc[f][nt][2]), "+f"(acc[f][nt][3])
                        : "r"(af[f][0]), "r"(af[f][1]), "r"(af[f][2]), "r"(af[f][3]),
                          "r"(bf[nt][0]), "r"(bf[nt][1]));
                }
        }
        __syncthreads();
    }

#pragma unroll
    for (int q = 0; q < 4; q++) {
        wsum[q] += __shfl_xor_sync(0xffffffffu, wsum[q], 1);
        wsum[q] += __shfl_xor_sync(0xffffffffu, wsum[q], 2);
    }

#pragma unroll
    for (int q = 0; q < 4; q++) {
        const bool good = mrow[q] && m2ok && (wsum[q] > 0.f);
        const float inv = 1.f / wsum[q];
        const int f = q >> 1;
        const int lohi = (q & 1) * 2;
        float* op = out + ((size_t)(b * N_ + rr[q])) * (H_ * D_) + hh * D_ + tg * 2;
#pragma unroll
        for (int nt = 0; nt < 8; nt++) {
            float2 v;
            v.x = good ? acc[f][nt][lohi + 0] * inv : 0.f;
            v.y = good ? acc[f][nt][lohi + 1] * inv : 0.f;
            *(float2*)(op + nt * 8) = v;
        }
    }
}

// ---------------------------------------------------------------------------
extern "C" void kernel_launch(void* const* d_in, const int* in_sizes, int n_in,
                              void* d_out, int out_size) {
    const float* h    = (const float*)d_in[0];   // [16,1024,256] f32
    const int*   mask = (const int*)  d_in[1];   // [16,1024] i32
    const float* W    = (const float*)d_in[2];   // [256,256] f32
    const float* a    = (const float*)d_in[3];   // [128,1] f32
    float* out = (float*)d_out;                  // [16,1024,256] f32

    k_gemm_tc<<<dim3(128, 4), 256>>>(h, W);
    k_scores <<<64, 256>>>(mask, a);
    k_attn_tc<<<dim3(N_ / 256, BH_), 256>>>(mask, out);
}

// round 10
// speedup vs baseline: 2.6950x; 1.0956x over previous
#include <cuda_runtime.h>
#include <cuda_bf16.h>

#define B_ 16
#define N_ 1024
#define F_ 256
#define H_ 4
#define D_ 64
#define BH_ (B_*H_)
#define NEG_SLOPE 0.2f
#define LOG2E 1.4426950408889634f

// Scratch (allocation-free rule: __device__ globals)
__device__ float g_Wh[(size_t)BH_ * N_ * D_];   // [b*H+h][n][d], 16 MB
__device__ float g_s1[BH_ * N_];
__device__ float g_s2[BH_ * N_];
__device__ float g_m2[BH_];                     // max over masked j of s2
// split-bf16 copies of h and W (hi + lo), filled by k_split
__device__ __nv_bfloat16 g_hA[(size_t)B_ * N_ * F_];
__device__ __nv_bfloat16 g_lA[(size_t)B_ * N_ * F_];
__device__ __nv_bfloat16 g_hW[F_ * F_];
__device__ __nv_bfloat16 g_lW[F_ * F_];

__device__ __forceinline__ float ex2f(float x) {
    float r; asm("ex2.approx.f32 %0, %1;" : "=f"(r) : "f"(x)); return r;
}
__device__ __forceinline__ unsigned cvt_tf32(float x) {
    unsigned r; asm("cvt.rna.tf32.f32 %0, %1;" : "=r"(r) : "f"(x)); return r;
}
__device__ __forceinline__ void cpa16(unsigned dst, const void* src) {
    asm volatile("cp.async.ca.shared.global [%0], [%1], 16;" :: "r"(dst), "l"(src));
}

#define MMA_BF16(d, a, b) asm volatile( \
    "mma.sync.aligned.m16n8k16.row.col.f32.bf16.bf16.f32 " \
    "{%0,%1,%2,%3}, {%4,%5,%6,%7}, {%8,%9}, {%0,%1,%2,%3};" \
    : "+f"((d)[0]), "+f"((d)[1]), "+f"((d)[2]), "+f"((d)[3]) \
    : "r"((a)[0]), "r"((a)[1]), "r"((a)[2]), "r"((a)[3]), \
      "r"((b)[0]), "r"((b)[1]))

// ---------------------------------------------------------------------------
// Kernel 0: one-shot split of h and W into bf16 hi/lo pairs.
// ---------------------------------------------------------------------------
#define NA4 ((size_t)B_ * N_ * F_ / 4)      // 1048576 float4's of h
#define NW4 ((size_t)F_ * F_ / 4)           // 16384 float4's of W
__global__ __launch_bounds__(256) void k_split(const float* __restrict__ h,
                                               const float* __restrict__ W) {
    size_t t = (size_t)blockIdx.x * 256 + threadIdx.x;
    if (t >= NA4 + NW4) return;
    const float4* src; __nv_bfloat16 *dh, *dl; size_t idx;
    if (t < NA4) { src = (const float4*)h; dh = g_hA; dl = g_lA; idx = t; }
    else         { src = (const float4*)W; dh = g_hW; dl = g_lW; idx = t - NA4; }
    float4 v = src[idx];
    float f[4] = {v.x, v.y, v.z, v.w};
    union { __nv_bfloat16 b[4]; uint2 u; } ph, pl;
#pragma unroll
    for (int e = 0; e < 4; e++) {
        __nv_bfloat16 hi = __float2bfloat16(f[e]);
        ph.b[e] = hi;
        pl.b[e] = __float2bfloat16(f[e] - __bfloat162float(hi));
    }
    *(uint2*)(dh + idx * 4) = ph.u;
    *(uint2*)(dl + idx * 4) = pl.u;
}

// ---------------------------------------------------------------------------
// Kernel A (tensor cores, cp.async pipelined): Wh = h @ W^T, split-bf16.
// grid (128, H=4), block 256 = 8 warps (4m x 2n). Tile M=128, N=64, K-chunk 16.
// Double-buffered LDGSTS; smem stride 24 bf16 -> conflict-free frag LDS
// (word bank = (12g + tg) mod 32, all 32 distinct).
// ---------------------------------------------------------------------------
#define KP 24                 // bf16 stride of one 16-wide k-chunk row
#define SZ_A (128 * KP * 2)   // bytes per A buffer (hi or lo): 6144
#define SZ_B (64 * KP * 2)    //                      B: 3072
#define OFF_AH 0
#define OFF_AL (2 * SZ_A)                 // 12288
#define OFF_BH (4 * SZ_A)                 // 24576
#define OFF_BL (4 * SZ_A + 2 * SZ_B)      // 30720
__global__ __launch_bounds__(256) void k_gemm_tc(const float* __restrict__ hun,
                                                 const float* __restrict__ Wun) {
    __shared__ __align__(16) char smem[4 * SZ_A + 4 * SZ_B];   // 36864 B

    const int tid  = threadIdx.x;
    const int warp = tid >> 5, lane = tid & 31;
    const int g  = lane >> 2;
    const int tg = lane & 3;
    const int wm = warp >> 1;
    const int wn = warp & 1;
    const int m0 = blockIdx.x * 128;
    const int head = blockIdx.y;
    const unsigned sb = (unsigned)__cvta_generic_to_shared(smem);

    // fetch lanes (fixed per thread)
    const int ar = tid >> 1,  ac = tid & 1;          // A: 128 rows x 2 chunks
    const int br = tid >> 2;                         // B: 64 rows x 2 chunks x hi/lo
    const int bc = (tid >> 1) & 1, bl = tid & 1;
    const __nv_bfloat16* srcAh = g_hA + (size_t)(m0 + ar) * F_ + ac * 8;
    const __nv_bfloat16* srcAl = g_lA + (size_t)(m0 + ar) * F_ + ac * 8;
    const __nv_bfloat16* srcB  = (bl ? g_lW : g_hW) + (size_t)(head * 64 + br) * F_ + bc * 8;
    const unsigned dA  = ar * (KP * 2) + ac * 16;
    const unsigned dB  = sb + (bl ? OFF_BL : OFF_BH) + br * (KP * 2) + bc * 16;

#define FETCH(kt, buf) do {                                         \
        int ko = (kt) * 16;                                         \
        cpa16(sb + OFF_AH + (buf) * SZ_A + dA, srcAh + ko);         \
        cpa16(sb + OFF_AL + (buf) * SZ_A + dA, srcAl + ko);         \
        cpa16(dB + (buf) * SZ_B, srcB + ko);                        \
        asm volatile("cp.async.commit_group;");                     \
    } while (0)

    float acc[2][4][4];
#pragma unroll
    for (int mf = 0; mf < 2; mf++)
#pragma unroll
        for (int nf = 0; nf < 4; nf++)
#pragma unroll
            for (int q = 0; q < 4; q++) acc[mf][nf][q] = 0.f;

    FETCH(0, 0);
    FETCH(1, 1);

    for (int kt = 0; kt < 16; kt++) {
        const int buf = kt & 1;
        if (kt < 15) asm volatile("cp.async.wait_group 1;");
        else         asm volatile("cp.async.wait_group 0;");
        __syncthreads();

        const __nv_bfloat16* Ah = (const __nv_bfloat16*)(smem + OFF_AH + buf * SZ_A);
        const __nv_bfloat16* Al = (const __nv_bfloat16*)(smem + OFF_AL + buf * SZ_A);
        const __nv_bfloat16* Bh = (const __nv_bfloat16*)(smem + OFF_BH + buf * SZ_B);
        const __nv_bfloat16* Bl = (const __nv_bfloat16*)(smem + OFF_BL + buf * SZ_B);
        const int kb = 2 * tg;

        unsigned ah[2][4], al[2][4], bh[4][2], blf[4][2];
#pragma unroll
        for (int mf = 0; mf < 2; mf++) {
            const int base = (wm * 32 + mf * 16 + g) * KP;
            ah[mf][0] = *(const unsigned*)&Ah[base + kb];
            ah[mf][1] = *(const unsigned*)&Ah[base + 8 * KP + kb];
            ah[mf][2] = *(const unsigned*)&Ah[base + kb + 8];
            ah[mf][3] = *(const unsigned*)&Ah[base + 8 * KP + kb + 8];
            al[mf][0] = *(const unsigned*)&Al[base + kb];
            al[mf][1] = *(const unsigned*)&Al[base + 8 * KP + kb];
            al[mf][2] = *(const unsigned*)&Al[base + kb + 8];
            al[mf][3] = *(const unsigned*)&Al[base + 8 * KP + kb + 8];
        }
#pragma unroll
        for (int nf = 0; nf < 4; nf++) {
            const int bb = (wn * 32 + nf * 8 + g) * KP + kb;
            bh[nf][0]  = *(const unsigned*)&Bh[bb];
            bh[nf][1]  = *(const unsigned*)&Bh[bb + 8];
            blf[nf][0] = *(const unsigned*)&Bl[bb];
            blf[nf][1] = *(const unsigned*)&Bl[bb + 8];
        }
#pragma unroll
        for (int mf = 0; mf < 2; mf++)
#pragma unroll
            for (int nf = 0; nf < 4; nf++) {
                MMA_BF16(acc[mf][nf], ah[mf], bh[nf]);
                MMA_BF16(acc[mf][nf], al[mf], bh[nf]);
                MMA_BF16(acc[mf][nf], ah[mf], blf[nf]);
            }
        __syncthreads();
        if (kt + 2 < 16) FETCH(kt + 2, buf);
    }

    // scatter to g_Wh[bh][n][d]
#pragma unroll
    for (int mf = 0; mf < 2; mf++) {
        const int row0 = m0 + wm * 32 + mf * 16 + g;
        const int b = row0 >> 10, n = row0 & 1023;
        float* base = g_Wh + ((size_t)(b * H_ + head) * N_ + n) * D_;
#pragma unroll
        for (int nf = 0; nf < 4; nf++) {
            const int d = wn * 32 + nf * 8 + 2 * tg;
            *(float2*)(base + d)          = make_float2(acc[mf][nf][0], acc[mf][nf][1]);
            *(float2*)(base + 8 * D_ + d) = make_float2(acc[mf][nf][2], acc[mf][nf][3]);
        }
    }
}

// ---------------------------------------------------------------------------
// Kernel B: s1,s2 per (bh,n) + masked max of s2 per bh. grid 64, block 256.
// ---------------------------------------------------------------------------
__global__ __launch_bounds__(256) void k_scores(const int* __restrict__ mask,
                                                const float* __restrict__ a) {
    __shared__ float sa[128];
    __shared__ float red[256];
    const int bh = blockIdx.x, b = bh >> 2, tid = threadIdx.x;
    if (tid < 128) sa[tid] = a[tid];
    __syncthreads();

    float lmax = -3.0e38f;
    for (int n = tid; n < N_; n += 256) {
        const float4* row = (const float4*)(g_Wh + ((size_t)bh * N_ + n) * D_);
        float s1 = 0.f, s2 = 0.f;
#pragma unroll
        for (int q = 0; q < 16; q++) {
            float4 v = row[q];
            s1 += v.x * sa[q*4+0] + v.y * sa[q*4+1] + v.z * sa[q*4+2] + v.w * sa[q*4+3];
            s2 += v.x * sa[64+q*4+0] + v.y * sa[64+q*4+1] + v.z * sa[64+q*4+2] + v.w * sa[64+q*4+3];
        }
        g_s1[bh * N_ + n] = s1;
        g_s2[bh * N_ + n] = s2;
        if (mask[b * N_ + n]) lmax = fmaxf(lmax, s2);
    }
    red[tid] = lmax;
    __syncthreads();
    for (int s = 128; s > 0; s >>= 1) {
        if (tid < s) red[tid] = fmaxf(red[tid], red[tid + s]);
        __syncthreads();
    }
    if (tid == 0) g_m2[bh] = red[0];
}

// ---------------------------------------------------------------------------
// Kernel C (tensor cores): h'[i,:] = softmax_j(f(s1_i+s2_j)) @ Wh.
// tf32 mma.m16n8k8; Wh tile pre-converted to tf32 bits at smem fill.
// grid (N/256=4, BH=64), block 256 (8 warps).
// ---------------------------------------------------------------------------
__global__ __launch_bounds__(256) void k_attn_tc(const int* __restrict__ mask,
                                                 float* __restrict__ out) {
    __shared__ unsigned sWh[128 * 72];   // 36 KB j-tile, tf32 bit patterns
    __shared__ float sS[128];
    const int bh = blockIdx.y, b = bh >> 2, hh = bh & 3;
    const int tid = threadIdx.x;
    const int warp = tid >> 5, lane = tid & 31;
    const int g  = lane >> 2;
    const int tg = lane & 3;
    const int ib = blockIdx.x * 256;

    const float m2 = g_m2[bh];
    const bool m2ok = (m2 > -1.0e29f);

    int r0 = ib + warp * 16 + g;
    int rr[4] = { r0, r0 + 8, r0 + 128, r0 + 136 };

    float s1v[4], rmL[4];
    int   mrow[4];
#pragma unroll
    for (int q = 0; q < 4; q++) {
        float s1 = g_s1[bh * N_ + rr[q]];
        float t0 = s1 + m2;
        float rm = fmaxf(t0, NEG_SLOPE * t0);    // leakyrelu (slope>0)
        s1v[q] = s1;
        rmL[q] = rm * LOG2E;
        mrow[q] = mask[b * N_ + rr[q]];
    }

    float acc[2][8][4];
#pragma unroll
    for (int f = 0; f < 2; f++)
#pragma unroll
        for (int nt = 0; nt < 8; nt++)
#pragma unroll
            for (int q = 0; q < 4; q++) acc[f][nt][q] = 0.f;
    float wsum[4] = {0.f, 0.f, 0.f, 0.f};

    for (int jt = 0; jt < N_; jt += 128) {
        {
            const float* src = g_Wh + ((size_t)bh * N_ + jt) * D_;
            int row = tid >> 1;
            int c0  = (tid & 1) * 32;
            const float4* s4 = (const float4*)(src + (size_t)row * D_ + c0);
            uint4* d4 = (uint4*)(sWh + row * 72 + c0);
#pragma unroll
            for (int q = 0; q < 8; q++) {
                float4 v = s4[q];
                uint4 u;
                u.x = cvt_tf32(v.x); u.y = cvt_tf32(v.y);
                u.z = cvt_tf32(v.z); u.w = cvt_tf32(v.w);
                d4[q] = u;
            }
        }
        if (tid < 128) {
            int j = jt + tid;
            sS[tid] = mask[b * N_ + j] ? g_s2[bh * N_ + j] : -1.0e30f;
        }
        __syncthreads();

#pragma unroll 1
        for (int ks = 0; ks < 16; ks++) {
            const int j0 = ks * 8;
            const float s2a = sS[j0 + tg];
            const float s2b = sS[j0 + 4 + tg];

            unsigned af[2][4];
#pragma unroll
            for (int f = 0; f < 2; f++) {
                float sA = s1v[f*2+0], rA = rmL[f*2+0];
                float sB = s1v[f*2+1], rB = rmL[f*2+1];
                float t;
                t = sA + s2a; float w0 = ex2f(fmaf(fmaxf(t, NEG_SLOPE*t), LOG2E, -rA));
                t = sB + s2a; float w1 = ex2f(fmaf(fmaxf(t, NEG_SLOPE*t), LOG2E, -rB));
                t = sA + s2b; float w2 = ex2f(fmaf(fmaxf(t, NEG_SLOPE*t), LOG2E, -rA));
                t = sB + s2b; float w3 = ex2f(fmaf(fmaxf(t, NEG_SLOPE*t), LOG2E, -rB));
                wsum[f*2+0] += w0 + w2;
                wsum[f*2+1] += w1 + w3;
                af[f][0] = cvt_tf32(w0); af[f][1] = cvt_tf32(w1);
                af[f][2] = cvt_tf32(w2); af[f][3] = cvt_tf32(w3);
            }

            const unsigned* p0 = sWh + (j0 + tg) * 72 + g;
            const unsigned* p1 = sWh + (j0 + 4 + tg) * 72 + g;
            unsigned bf[8][2];
#pragma unroll
            for (int nt = 0; nt < 8; nt++) {
                bf[nt][0] = p0[nt * 8];
                bf[nt][1] = p1[nt * 8];
            }

#pragma unroll
            for (int f = 0; f < 2; f++)
#pragma unroll
                for (int nt = 0; nt < 8; nt++) {
                    asm volatile(
                        "mma.sync.aligned.m16n8k8.row.col.f32.tf32.tf32.f32 "
                        "{%0,%1,%2,%3}, {%4,%5,%6,%7}, {%8,%9}, {%0,%1,%2,%3};"
                        : "+f"(acc[f][nt][0]), "+f"(acc[f][nt][1]),
                          "+f"(acc[f][nt][2]), "+f"(acc[f][nt][3])
                        : "r"(af[f][0]), "r"(af[f][1]), "r"(af[f][2]), "r"(af[f][3]),
                          "r"(bf[nt][0]), "r"(bf[nt][1]));
                }
        }
        __syncthreads();
    }

#pragma unroll
    for (int q = 0; q < 4; q++) {
        wsum[q] += __shfl_xor_sync(0xffffffffu, wsum[q], 1);
        wsum[q] += __shfl_xor_sync(0xffffffffu, wsum[q], 2);
    }

#pragma unroll
    for (int q = 0; q < 4; q++) {
        const bool good = mrow[q] && m2ok && (wsum[q] > 0.f);
        const float inv = 1.f / wsum[q];
        const int f = q >> 1;
        const int lohi = (q & 1) * 2;
        float* op = out + ((size_t)(b * N_ + rr[q])) * (H_ * D_) + hh * D_ + tg * 2;
#pragma unroll
        for (int nt = 0; nt < 8; nt++) {
            float2 v;
            v.x = good ? acc[f][nt][lohi + 0] * inv : 0.f;
            v.y = good ? acc[f][nt][lohi + 1] * inv : 0.f;
            *(float2*)(op + nt * 8) = v;
        }
    }
}

// ---------------------------------------------------------------------------
extern "C" void kernel_launch(void* const* d_in, const int* in_sizes, int n_in,
                              void* d_out, int out_size) {
    const float* h    = (const float*)d_in[0];   // [16,1024,256] f32
    const int*   mask = (const int*)  d_in[1];   // [16,1024] i32
    const float* W    = (const float*)d_in[2];   // [256,256] f32
    const float* a    = (const float*)d_in[3];   // [128,1] f32
    float* out = (float*)d_out;                  // [16,1024,256] f32

    int nsplit = (int)((NA4 + NW4 + 255) / 256);
    k_split  <<<nsplit, 256>>>(h, W);
    k_gemm_tc<<<dim3(128, 4), 256>>>(h, W);
    k_scores <<<64, 256>>>(mask, a);
    k_attn_tc<<<dim3(N_ / 256, BH_), 256>>>(mask, out);
}

// round 11
// speedup vs baseline: 2.9649x; 1.1002x over previous
#include <cuda_runtime.h>
#include <cuda_bf16.h>

#define B_ 16
#define N_ 1024
#define F_ 256
#define H_ 4
#define D_ 64
#define BH_ (B_*H_)
#define NEG_SLOPE 0.2f
#define LOG2E 1.4426950408889634f

// Scratch (allocation-free rule: __device__ globals)
__device__ float    g_Wh[(size_t)BH_ * N_ * D_];  // fp32 Wh (scores)
__device__ unsigned g_Wt[(size_t)BH_ * N_ * D_];  // tf32-bit Wh (attn B operand)
__device__ float g_s1[BH_ * N_];
__device__ float g_s2[BH_ * N_];
__device__ float g_m2[BH_];
// split-bf16 copies of h and W (hi + lo), filled by k_split
__device__ __nv_bfloat16 g_hA[(size_t)B_ * N_ * F_];
__device__ __nv_bfloat16 g_lA[(size_t)B_ * N_ * F_];
__device__ __nv_bfloat16 g_hW[F_ * F_];
__device__ __nv_bfloat16 g_lW[F_ * F_];

__device__ __forceinline__ float ex2f(float x) {
    float r; asm("ex2.approx.f32 %0, %1;" : "=f"(r) : "f"(x)); return r;
}
__device__ __forceinline__ unsigned cvt_tf32(float x) {
    unsigned r; asm("cvt.rna.tf32.f32 %0, %1;" : "=r"(r) : "f"(x)); return r;
}
__device__ __forceinline__ void cpa16(unsigned dst, const void* src) {
    asm volatile("cp.async.ca.shared.global [%0], [%1], 16;" :: "r"(dst), "l"(src));
}

#define MMA_BF16(d, a, b) asm volatile( \
    "mma.sync.aligned.m16n8k16.row.col.f32.bf16.bf16.f32 " \
    "{%0,%1,%2,%3}, {%4,%5,%6,%7}, {%8,%9}, {%0,%1,%2,%3};" \
    : "+f"((d)[0]), "+f"((d)[1]), "+f"((d)[2]), "+f"((d)[3]) \
    : "r"((a)[0]), "r"((a)[1]), "r"((a)[2]), "r"((a)[3]), \
      "r"((b)[0]), "r"((b)[1]))

// ---------------------------------------------------------------------------
// Kernel 0: one-shot split of h and W into bf16 hi/lo pairs.
// ---------------------------------------------------------------------------
#define NA4 ((size_t)B_ * N_ * F_ / 4)
#define NW4 ((size_t)F_ * F_ / 4)
__global__ __launch_bounds__(256) void k_split(const float* __restrict__ h,
                                               const float* __restrict__ W) {
    size_t t = (size_t)blockIdx.x * 256 + threadIdx.x;
    if (t >= NA4 + NW4) return;
    const float4* src; __nv_bfloat16 *dh, *dl; size_t idx;
    if (t < NA4) { src = (const float4*)h; dh = g_hA; dl = g_lA; idx = t; }
    else         { src = (const float4*)W; dh = g_hW; dl = g_lW; idx = t - NA4; }
    float4 v = src[idx];
    float f[4] = {v.x, v.y, v.z, v.w};
    union { __nv_bfloat16 b[4]; uint2 u; } ph, pl;
#pragma unroll
    for (int e = 0; e < 4; e++) {
        __nv_bfloat16 hi = __float2bfloat16(f[e]);
        ph.b[e] = hi;
        pl.b[e] = __float2bfloat16(f[e] - __bfloat162float(hi));
    }
    *(uint2*)(dh + idx * 4) = ph.u;
    *(uint2*)(dl + idx * 4) = pl.u;
}

// ---------------------------------------------------------------------------
// Kernel A (tensor cores, cp.async pipelined): Wh = h @ W^T, split-bf16.
// Epilogue dual-stores fp32 Wh (scores) and tf32-bit Wh (attn).
// ---------------------------------------------------------------------------
#define KP 24
#define SZ_A (128 * KP * 2)
#define SZ_B (64 * KP * 2)
#define OFF_AH 0
#define OFF_AL (2 * SZ_A)
#define OFF_BH (4 * SZ_A)
#define OFF_BL (4 * SZ_A + 2 * SZ_B)
__global__ __launch_bounds__(256) void k_gemm_tc(const float* __restrict__ hun,
                                                 const float* __restrict__ Wun) {
    __shared__ __align__(16) char smem[4 * SZ_A + 4 * SZ_B];

    const int tid  = threadIdx.x;
    const int warp = tid >> 5, lane = tid & 31;
    const int g  = lane >> 2;
    const int tg = lane & 3;
    const int wm = warp >> 1;
    const int wn = warp & 1;
    const int m0 = blockIdx.x * 128;
    const int head = blockIdx.y;
    const unsigned sb = (unsigned)__cvta_generic_to_shared(smem);

    const int ar = tid >> 1,  ac = tid & 1;
    const int br = tid >> 2;
    const int bc = (tid >> 1) & 1, bl = tid & 1;
    const __nv_bfloat16* srcAh = g_hA + (size_t)(m0 + ar) * F_ + ac * 8;
    const __nv_bfloat16* srcAl = g_lA + (size_t)(m0 + ar) * F_ + ac * 8;
    const __nv_bfloat16* srcB  = (bl ? g_lW : g_hW) + (size_t)(head * 64 + br) * F_ + bc * 8;
    const unsigned dA  = ar * (KP * 2) + ac * 16;
    const unsigned dB  = sb + (bl ? OFF_BL : OFF_BH) + br * (KP * 2) + bc * 16;

#define FETCH(kt, buf) do {                                         \
        int ko = (kt) * 16;                                         \
        cpa16(sb + OFF_AH + (buf) * SZ_A + dA, srcAh + ko);         \
        cpa16(sb + OFF_AL + (buf) * SZ_A + dA, srcAl + ko);         \
        cpa16(dB + (buf) * SZ_B, srcB + ko);                        \
        asm volatile("cp.async.commit_group;");                     \
    } while (0)

    float acc[2][4][4];
#pragma unroll
    for (int mf = 0; mf < 2; mf++)
#pragma unroll
        for (int nf = 0; nf < 4; nf++)
#pragma unroll
            for (int q = 0; q < 4; q++) acc[mf][nf][q] = 0.f;

    FETCH(0, 0);
    FETCH(1, 1);

    for (int kt = 0; kt < 16; kt++) {
        const int buf = kt & 1;
        if (kt < 15) asm volatile("cp.async.wait_group 1;");
        else         asm volatile("cp.async.wait_group 0;");
        __syncthreads();

        const __nv_bfloat16* Ah = (const __nv_bfloat16*)(smem + OFF_AH + buf * SZ_A);
        const __nv_bfloat16* Al = (const __nv_bfloat16*)(smem + OFF_AL + buf * SZ_A);
        const __nv_bfloat16* Bh = (const __nv_bfloat16*)(smem + OFF_BH + buf * SZ_B);
        const __nv_bfloat16* Bl = (const __nv_bfloat16*)(smem + OFF_BL + buf * SZ_B);
        const int kb = 2 * tg;

        unsigned ah[2][4], al[2][4], bh[4][2], blf[4][2];
#pragma unroll
        for (int mf = 0; mf < 2; mf++) {
            const int base = (wm * 32 + mf * 16 + g) * KP;
            ah[mf][0] = *(const unsigned*)&Ah[base + kb];
            ah[mf][1] = *(const unsigned*)&Ah[base + 8 * KP + kb];
            ah[mf][2] = *(const unsigned*)&Ah[base + kb + 8];
            ah[mf][3] = *(const unsigned*)&Ah[base + 8 * KP + kb + 8];
            al[mf][0] = *(const unsigned*)&Al[base + kb];
            al[mf][1] = *(const unsigned*)&Al[base + 8 * KP + kb];
            al[mf][2] = *(const unsigned*)&Al[base + kb + 8];
            al[mf][3] = *(const unsigned*)&Al[base + 8 * KP + kb + 8];
        }
#pragma unroll
        for (int nf = 0; nf < 4; nf++) {
            const int bb = (wn * 32 + nf * 8 + g) * KP + kb;
            bh[nf][0]  = *(const unsigned*)&Bh[bb];
            bh[nf][1]  = *(const unsigned*)&Bh[bb + 8];
            blf[nf][0] = *(const unsigned*)&Bl[bb];
            blf[nf][1] = *(const unsigned*)&Bl[bb + 8];
        }
#pragma unroll
        for (int mf = 0; mf < 2; mf++)
#pragma unroll
            for (int nf = 0; nf < 4; nf++) {
                MMA_BF16(acc[mf][nf], ah[mf], bh[nf]);
                MMA_BF16(acc[mf][nf], al[mf], bh[nf]);
                MMA_BF16(acc[mf][nf], ah[mf], blf[nf]);
            }
        __syncthreads();
        if (kt + 2 < 16) FETCH(kt + 2, buf);
    }

    // scatter to g_Wh (fp32) + g_Wt (tf32 bits)
#pragma unroll
    for (int mf = 0; mf < 2; mf++) {
        const int row0 = m0 + wm * 32 + mf * 16 + g;
        const int b = row0 >> 10, n = row0 & 1023;
        const size_t base = ((size_t)(b * H_ + head) * N_ + n) * D_;
#pragma unroll
        for (int nf = 0; nf < 4; nf++) {
            const int d = wn * 32 + nf * 8 + 2 * tg;
            *(float2*)(g_Wh + base + d) = make_float2(acc[mf][nf][0], acc[mf][nf][1]);
            *(float2*)(g_Wh + base + 8 * D_ + d) = make_float2(acc[mf][nf][2], acc[mf][nf][3]);
            *(uint2*)(g_Wt + base + d) =
                make_uint2(cvt_tf32(acc[mf][nf][0]), cvt_tf32(acc[mf][nf][1]));
            *(uint2*)(g_Wt + base + 8 * D_ + d) =
                make_uint2(cvt_tf32(acc[mf][nf][2]), cvt_tf32(acc[mf][nf][3]));
        }
    }
}

// ---------------------------------------------------------------------------
// Kernel B: s1,s2 per (bh,n) + masked max of s2 per bh. grid 64, block 256.
// ---------------------------------------------------------------------------
__global__ __launch_bounds__(256) void k_scores(const int* __restrict__ mask,
                                                const float* __restrict__ a) {
    __shared__ float sa[128];
    __shared__ float red[256];
    const int bh = blockIdx.x, b = bh >> 2, tid = threadIdx.x;
    if (tid < 128) sa[tid] = a[tid];
    __syncthreads();

    float lmax = -3.0e38f;
    for (int n = tid; n < N_; n += 256) {
        const float4* row = (const float4*)(g_Wh + ((size_t)bh * N_ + n) * D_);
        float s1 = 0.f, s2 = 0.f;
#pragma unroll
        for (int q = 0; q < 16; q++) {
            float4 v = row[q];
            s1 += v.x * sa[q*4+0] + v.y * sa[q*4+1] + v.z * sa[q*4+2] + v.w * sa[q*4+3];
            s2 += v.x * sa[64+q*4+0] + v.y * sa[64+q*4+1] + v.z * sa[64+q*4+2] + v.w * sa[64+q*4+3];
        }
        g_s1[bh * N_ + n] = s1;
        g_s2[bh * N_ + n] = s2;
        if (mask[b * N_ + n]) lmax = fmaxf(lmax, s2);
    }
    red[tid] = lmax;
    __syncthreads();
    for (int s = 128; s > 0; s >>= 1) {
        if (tid < s) red[tid] = fmaxf(red[tid], red[tid + s]);
        __syncthreads();
    }
    if (tid == 0) g_m2[bh] = red[0];
}

// ---------------------------------------------------------------------------
// Kernel C (tensor cores, cp.async pipelined): softmax(P) @ Wh.
// tf32 mma.m16n8k8; Wh tiles arrive pre-converted (g_Wt) via LDGSTS,
// double-buffered 64-row j-tiles, stride 72 (conflict-free B frag LDS).
// grid (N/256=4, BH=64), block 256 (8 warps).
// ---------------------------------------------------------------------------
#define TJ 64
#define SWSTR 72
#define SZT (TJ * SWSTR * 4)   // 18432 bytes per buffer
__global__ __launch_bounds__(256) void k_attn_tc(const int* __restrict__ mask,
                                                 float* __restrict__ out) {
    __shared__ __align__(16) unsigned sWh[2][TJ * SWSTR];
    __shared__ float sS[2][TJ];
    const int bh = blockIdx.y, b = bh >> 2, hh = bh & 3;
    const int tid = threadIdx.x;
    const int warp = tid >> 5, lane = tid & 31;
    const int g  = lane >> 2;
    const int tg = lane & 3;
    const int ib = blockIdx.x * 256;
    const unsigned sbW = (unsigned)__cvta_generic_to_shared(sWh);

    const float m2 = g_m2[bh];
    const bool m2ok = (m2 > -1.0e29f);

    int r0 = ib + warp * 16 + g;
    int rr[4] = { r0, r0 + 8, r0 + 128, r0 + 136 };

    float s1v[4], rmL[4];
    int   mrow[4];
#pragma unroll
    for (int q = 0; q < 4; q++) {
        float s1 = g_s1[bh * N_ + rr[q]];
        float t0 = s1 + m2;
        float rm = fmaxf(t0, NEG_SLOPE * t0);
        s1v[q] = s1;
        rmL[q] = rm * LOG2E;
        mrow[q] = mask[b * N_ + rr[q]];
    }

    const unsigned* WtB = g_Wt + (size_t)bh * N_ * D_;

    // fill helpers: 1024 16B chunks per tile, 4 per thread, fully coalesced
#define FILLJ(tile, buf) do {                                              \
        const unsigned* srcW = WtB + (size_t)(tile) * TJ * D_;             \
        _Pragma("unroll")                                                  \
        for (int q = 0; q < 4; q++) {                                      \
            int id  = tid + 256 * q;                                       \
            int row = id >> 4, c = id & 15;                                \
            cpa16(sbW + (buf) * SZT + row * (SWSTR * 4) + c * 16,          \
                  srcW + row * D_ + c * 4);                                \
        }                                                                  \
        asm volatile("cp.async.commit_group;");                            \
    } while (0)
#define FILLS(tile, buf) do {                                              \
        if (tid < TJ) {                                                    \
            int j = (tile) * TJ + tid;                                     \
            sS[buf][tid] = mask[b * N_ + j] ? g_s2[bh * N_ + j] : -1.0e30f;\
        }                                                                  \
    } while (0)

    float acc[2][8][4];
#pragma unroll
    for (int f = 0; f < 2; f++)
#pragma unroll
        for (int nt = 0; nt < 8; nt++)
#pragma unroll
            for (int q = 0; q < 4; q++) acc[f][nt][q] = 0.f;
    float wsum[4] = {0.f, 0.f, 0.f, 0.f};

    FILLJ(0, 0);
    FILLJ(1, 1);
    FILLS(0, 0);
    FILLS(1, 1);

    for (int t = 0; t < N_ / TJ; t++) {
        const int buf = t & 1;
        if (t < N_ / TJ - 1) asm volatile("cp.async.wait_group 1;");
        else                 asm volatile("cp.async.wait_group 0;");
        __syncthreads();

        const unsigned* tile = sWh[buf];
        const float*    sSt  = sS[buf];

#pragma unroll 1
        for (int ks = 0; ks < TJ / 8; ks++) {
            const int j0 = ks * 8;
            const float s2a = sSt[j0 + tg];
            const float s2b = sSt[j0 + 4 + tg];

            unsigned af[2][4];
#pragma unroll
            for (int f = 0; f < 2; f++) {
                float sA = s1v[f*2+0], rA = rmL[f*2+0];
                float sB = s1v[f*2+1], rB = rmL[f*2+1];
                float tt;
                tt = sA + s2a; float w0 = ex2f(fmaf(fmaxf(tt, NEG_SLOPE*tt), LOG2E, -rA));
                tt = sB + s2a; float w1 = ex2f(fmaf(fmaxf(tt, NEG_SLOPE*tt), LOG2E, -rB));
                tt = sA + s2b; float w2 = ex2f(fmaf(fmaxf(tt, NEG_SLOPE*tt), LOG2E, -rA));
                tt = sB + s2b; float w3 = ex2f(fmaf(fmaxf(tt, NEG_SLOPE*tt), LOG2E, -rB));
                wsum[f*2+0] += w0 + w2;
                wsum[f*2+1] += w1 + w3;
                af[f][0] = cvt_tf32(w0); af[f][1] = cvt_tf32(w1);
                af[f][2] = cvt_tf32(w2); af[f][3] = cvt_tf32(w3);
            }

            const unsigned* p0 = tile + (j0 + tg) * SWSTR + g;
            const unsigned* p1 = tile + (j0 + 4 + tg) * SWSTR + g;
            unsigned bf[8][2];
#pragma unroll
            for (int nt = 0; nt < 8; nt++) {
                bf[nt][0] = p0[nt * 8];
                bf[nt][1] = p1[nt * 8];
            }

#pragma unroll
            for (int f = 0; f < 2; f++)
#pragma unroll
                for (int nt = 0; nt < 8; nt++) {
                    asm volatile(
                        "mma.sync.aligned.m16n8k8.row.col.f32.tf32.tf32.f32 "
                        "{%0,%1,%2,%3}, {%4,%5,%6,%7}, {%8,%9}, {%0,%1,%2,%3};"
                        : "+f"(acc[f][nt][0]), "+f"(acc[f][nt][1]),
                          "+f"(acc[f][nt][2]), "+f"(acc[f][nt][3])
                        : "r"(af[f][0]), "r"(af[f][1]), "r"(af[f][2]), "r"(af[f][3]),
                          "r"(bf[nt][0]), "r"(bf[nt][1]));
                }
        }
        __syncthreads();
        if (t + 2 < N_ / TJ) {
            FILLJ(t + 2, buf);
            FILLS(t + 2, buf);
        }
    }

#pragma unroll
    for (int q = 0; q < 4; q++) {
        wsum[q] += __shfl_xor_sync(0xffffffffu, wsum[q], 1);
        wsum[q] += __shfl_xor_sync(0xffffffffu, wsum[q], 2);
    }

#pragma unroll
    for (int q = 0; q < 4; q++) {
        const bool good = mrow[q] && m2ok && (wsum[q] > 0.f);
        const float inv = 1.f / wsum[q];
        const int f = q >> 1;
        const int lohi = (q & 1) * 2;
        float* op = out + ((size_t)(b * N_ + rr[q])) * (H_ * D_) + hh * D_ + tg * 2;
#pragma unroll
        for (int nt = 0; nt < 8; nt++) {
            float2 v;
            v.x = good ? acc[f][nt][lohi + 0] * inv : 0.f;
            v.y = good ? acc[f][nt][lohi + 1] * inv : 0.f;
            *(float2*)(op + nt * 8) = v;
        }
    }
}

// ---------------------------------------------------------------------------
extern "C" void kernel_launch(void* const* d_in, const int* in_sizes, int n_in,
                              void* d_out, int out_size) {
    const float* h    = (const float*)d_in[0];   // [16,1024,256] f32
    const int*   mask = (const int*)  d_in[1];   // [16,1024] i32
    const float* W    = (const float*)d_in[2];   // [256,256] f32
    const float* a    = (const float*)d_in[3];   // [128,1] f32
    float* out = (float*)d_out;                  // [16,1024,256] f32

    int nsplit = (int)((NA4 + NW4 + 255) / 256);
    k_split  <<<nsplit, 256>>>(h, W);
    k_gemm_tc<<<dim3(128, 4), 256>>>(h, W);
    k_scores <<<64, 256>>>(mask, a);
    k_attn_tc<<<dim3(N_ / 256, BH_), 256>>>(mask, out);
}

// round 13
// speedup vs baseline: 3.0381x; 1.0247x over previous
#include <cuda_runtime.h>
#include <cuda_bf16.h>

#define B_ 16
#define N_ 1024
#define F_ 256
#define H_ 4
#define D_ 64
#define BH_ (B_*H_)
#define NEG_SLOPE 0.2f
#define LOG2E 1.4426950408889634f

// Scratch (allocation-free rule: __device__ globals)
__device__ float    g_Wh[(size_t)BH_ * N_ * D_];  // fp32 Wh (scores)
// tf32-bit Wh, interleaved for LDS.64 B-fragments:
// off(j,d) = (j>>3)*512 + d*8 + (j&3)*2 + ((j>>2)&1)   (per bh)
__device__ unsigned g_Wt[(size_t)BH_ * N_ * D_];
__device__ float g_s1[BH_ * N_];    // s1 * log2e
__device__ float g_s2[BH_ * N_];    // s2 * log2e
__device__ float g_m2[BH_];         // max over masked j of prescaled s2
// split-bf16 copies of h and W (hi + lo), filled by k_split
__device__ __nv_bfloat16 g_hA[(size_t)B_ * N_ * F_];
__device__ __nv_bfloat16 g_lA[(size_t)B_ * N_ * F_];
__device__ __nv_bfloat16 g_hW[F_ * F_];
__device__ __nv_bfloat16 g_lW[F_ * F_];

__device__ __forceinline__ float ex2f(float x) {
    float r; asm("ex2.approx.f32 %0, %1;" : "=f"(r) : "f"(x)); return r;
}
__device__ __forceinline__ unsigned cvt_tf32(float x) {
    unsigned r; asm("cvt.rna.tf32.f32 %0, %1;" : "=r"(r) : "f"(x)); return r;
}
__device__ __forceinline__ void cpa16(unsigned dst, const void* src) {
    asm volatile("cp.async.ca.shared.global [%0], [%1], 16;" :: "r"(dst), "l"(src));
}

#define MMA_BF16(d, a, b) asm volatile( \
    "mma.sync.aligned.m16n8k16.row.col.f32.bf16.bf16.f32 " \
    "{%0,%1,%2,%3}, {%4,%5,%6,%7}, {%8,%9}, {%0,%1,%2,%3};" \
    : "+f"((d)[0]), "+f"((d)[1]), "+f"((d)[2]), "+f"((d)[3]) \
    : "r"((a)[0]), "r"((a)[1]), "r"((a)[2]), "r"((a)[3]), \
      "r"((b)[0]), "r"((b)[1]))

// ---------------------------------------------------------------------------
// Kernel 0: one-shot split of h and W into bf16 hi/lo pairs.
// ---------------------------------------------------------------------------
#define NA4 ((size_t)B_ * N_ * F_ / 4)
#define NW4 ((size_t)F_ * F_ / 4)
__global__ __launch_bounds__(256) void k_split(const float* __restrict__ h,
                                               const float* __restrict__ W) {
    size_t t = (size_t)blockIdx.x * 256 + threadIdx.x;
    if (t >= NA4 + NW4) return;
    const float4* src; __nv_bfloat16 *dh, *dl; size_t idx;
    if (t < NA4) { src = (const float4*)h; dh = g_hA; dl = g_lA; idx = t; }
    else         { src = (const float4*)W; dh = g_hW; dl = g_lW; idx = t - NA4; }
    float4 v = src[idx];
    float f[4] = {v.x, v.y, v.z, v.w};
    union { __nv_bfloat16 b[4]; uint2 u; } ph, pl;
#pragma unroll
    for (int e = 0; e < 4; e++) {
        __nv_bfloat16 hi = __float2bfloat16(f[e]);
        ph.b[e] = hi;
        pl.b[e] = __float2bfloat16(f[e] - __bfloat162float(hi));
    }
    *(uint2*)(dh + idx * 4) = ph.u;
    *(uint2*)(dl + idx * 4) = pl.u;
}

// ---------------------------------------------------------------------------
// Kernel A (tensor cores, cp.async pipelined): Wh = h @ W^T, split-bf16.
// Epilogue dual-stores fp32 Wh (scores) and interleaved tf32-bit Wh (attn).
// ---------------------------------------------------------------------------
#define KP 24
#define SZ_A (128 * KP * 2)
#define SZ_B (64 * KP * 2)
#define OFF_AH 0
#define OFF_AL (2 * SZ_A)
#define OFF_BH (4 * SZ_A)
#define OFF_BL (4 * SZ_A + 2 * SZ_B)
__global__ __launch_bounds__(256) void k_gemm_tc(const float* __restrict__ hun,
                                                 const float* __restrict__ Wun) {
    __shared__ __align__(16) char smem[4 * SZ_A + 4 * SZ_B];

    const int tid  = threadIdx.x;
    const int warp = tid >> 5, lane = tid & 31;
    const int g  = lane >> 2;
    const int tg = lane & 3;
    const int wm = warp >> 1;
    const int wn = warp & 1;
    const int m0 = blockIdx.x * 128;
    const int head = blockIdx.y;
    const unsigned sb = (unsigned)__cvta_generic_to_shared(smem);

    const int ar = tid >> 1,  ac = tid & 1;
    const int br = tid >> 2;
    const int bc = (tid >> 1) & 1, bl = tid & 1;
    const __nv_bfloat16* srcAh = g_hA + (size_t)(m0 + ar) * F_ + ac * 8;
    const __nv_bfloat16* srcAl = g_lA + (size_t)(m0 + ar) * F_ + ac * 8;
    const __nv_bfloat16* srcB  = (bl ? g_lW : g_hW) + (size_t)(head * 64 + br) * F_ + bc * 8;
    const unsigned dA  = ar * (KP * 2) + ac * 16;
    const unsigned dB  = sb + (bl ? OFF_BL : OFF_BH) + br * (KP * 2) + bc * 16;

#define FETCH(kt, buf) do {                                         \
        int ko = (kt) * 16;                                         \
        cpa16(sb + OFF_AH + (buf) * SZ_A + dA, srcAh + ko);         \
        cpa16(sb + OFF_AL + (buf) * SZ_A + dA, srcAl + ko);         \
        cpa16(dB + (buf) * SZ_B, srcB + ko);                        \
        asm volatile("cp.async.commit_group;");                     \
    } while (0)

    float acc[2][4][4];
#pragma unroll
    for (int mf = 0; mf < 2; mf++)
#pragma unroll
        for (int nf = 0; nf < 4; nf++)
#pragma unroll
            for (int q = 0; q < 4; q++) acc[mf][nf][q] = 0.f;

    FETCH(0, 0);
    FETCH(1, 1);

    for (int kt = 0; kt < 16; kt++) {
        const int buf = kt & 1;
        if (kt < 15) asm volatile("cp.async.wait_group 1;");
        else         asm volatile("cp.async.wait_group 0;");
        __syncthreads();

        const __nv_bfloat16* Ah = (const __nv_bfloat16*)(smem + OFF_AH + buf * SZ_A);
        const __nv_bfloat16* Al = (const __nv_bfloat16*)(smem + OFF_AL + buf * SZ_A);
        const __nv_bfloat16* Bh = (const __nv_bfloat16*)(smem + OFF_BH + buf * SZ_B);
        const __nv_bfloat16* Bl = (const __nv_bfloat16*)(smem + OFF_BL + buf * SZ_B);
        const int kb = 2 * tg;

        unsigned ah[2][4], al[2][4], bh[4][2], blf[4][2];
#pragma unroll
        for (int mf = 0; mf < 2; mf++) {
            const int base = (wm * 32 + mf * 16 + g) * KP;
            ah[mf][0] = *(const unsigned*)&Ah[base + kb];
            ah[mf][1] = *(const unsigned*)&Ah[base + 8 * KP + kb];
            ah[mf][2] = *(const unsigned*)&Ah[base + kb + 8];
            ah[mf][3] = *(const unsigned*)&Ah[base + 8 * KP + kb + 8];
            al[mf][0] = *(const unsigned*)&Al[base + kb];
            al[mf][1] = *(const unsigned*)&Al[base + 8 * KP + kb];
            al[mf][2] = *(const unsigned*)&Al[base + kb + 8];
            al[mf][3] = *(const unsigned*)&Al[base + 8 * KP + kb + 8];
        }
#pragma unroll
        for (int nf = 0; nf < 4; nf++) {
            const int bb = (wn * 32 + nf * 8 + g) * KP + kb;
            bh[nf][0]  = *(const unsigned*)&Bh[bb];
            bh[nf][1]  = *(const unsigned*)&Bh[bb + 8];
            blf[nf][0] = *(const unsigned*)&Bl[bb];
            blf[nf][1] = *(const unsigned*)&Bl[bb + 8];
        }
#pragma unroll
        for (int mf = 0; mf < 2; mf++)
#pragma unroll
            for (int nf = 0; nf < 4; nf++) {
                MMA_BF16(acc[mf][nf], ah[mf], bh[nf]);
                MMA_BF16(acc[mf][nf], al[mf], bh[nf]);
                MMA_BF16(acc[mf][nf], ah[mf], blf[nf]);
            }
        __syncthreads();
        if (kt + 2 < 16) FETCH(kt + 2, buf);
    }

    // scatter: fp32 -> g_Wh, tf32 bits -> g_Wt (interleaved layout)
#pragma unroll
    for (int mf = 0; mf < 2; mf++) {
        const int row0 = m0 + wm * 32 + mf * 16 + g;
        const int b = row0 >> 10, n = row0 & 1023;
        const size_t base  = ((size_t)(b * H_ + head) * N_ + n) * D_;
        const size_t tbase = (size_t)(b * H_ + head) * N_ * D_;
        unsigned* wp = g_Wt + tbase + (size_t)(n >> 3) * 512 + (n & 3) * 2 + ((n >> 2) & 1);
#pragma unroll
        for (int nf = 0; nf < 4; nf++) {
            const int d = wn * 32 + nf * 8 + 2 * tg;
            *(float2*)(g_Wh + base + d) = make_float2(acc[mf][nf][0], acc[mf][nf][1]);
            *(float2*)(g_Wh + base + 8 * D_ + d) = make_float2(acc[mf][nf][2], acc[mf][nf][3]);
            wp[d * 8]           = cvt_tf32(acc[mf][nf][0]);   // (n,   d)
            wp[d * 8 + 8]       = cvt_tf32(acc[mf][nf][1]);   // (n,   d+1)
            wp[512 + d * 8]     = cvt_tf32(acc[mf][nf][2]);   // (n+8, d)
            wp[512 + d * 8 + 8] = cvt_tf32(acc[mf][nf][3]);   // (n+8, d+1)
        }
    }
}

// ---------------------------------------------------------------------------
// Kernel B: prescaled s1,s2 (x log2e) per (bh,n) + masked max of s2'.
// ---------------------------------------------------------------------------
__global__ __launch_bounds__(256) void k_scores(const int* __restrict__ mask,
                                                const float* __restrict__ a) {
    __shared__ float sa[128];
    __shared__ float red[256];
    const int bh = blockIdx.x, b = bh >> 2, tid = threadIdx.x;
    if (tid < 128) sa[tid] = a[tid];
    __syncthreads();

    float lmax = -3.0e38f;
    for (int n = tid; n < N_; n += 256) {
        const float4* row = (const float4*)(g_Wh + ((size_t)bh * N_ + n) * D_);
        float s1 = 0.f, s2 = 0.f;
#pragma unroll
        for (int q = 0; q < 16; q++) {
            float4 v = row[q];
            s1 += v.x * sa[q*4+0] + v.y * sa[q*4+1] + v.z * sa[q*4+2] + v.w * sa[q*4+3];
            s2 += v.x * sa[64+q*4+0] + v.y * sa[64+q*4+1] + v.z * sa[64+q*4+2] + v.w * sa[64+q*4+3];
        }
        s1 *= LOG2E;
        s2 *= LOG2E;
        g_s1[bh * N_ + n] = s1;
        g_s2[bh * N_ + n] = s2;
        if (mask[b * N_ + n]) lmax = fmaxf(lmax, s2);
    }
    red[tid] = lmax;
    __syncthreads();
    for (int s = 128; s > 0; s >>= 1) {
        if (tid < s) red[tid] = fmaxf(red[tid], red[tid + s]);
        __syncthreads();
    }
    if (tid == 0) g_m2[bh] = red[0];
}

// ---------------------------------------------------------------------------
// Kernel C (tensor cores, cp.async pipelined): softmax(P) @ Wh.
// tf32 mma.m16n8k8. Weights: 2 FADD + FMAX + ex2 (+ IADD tf32-round).
// B fragments: LDS.64 from interleaved tiles (conflict-free, no padding).
// grid (N/256=4, BH=64), block 256 (8 warps).
// ---------------------------------------------------------------------------
#define TJ 64
#define SZT (TJ * D_ * 4)   // 16384 bytes per buffer
__global__ __launch_bounds__(256, 2) void k_attn_tc(const int* __restrict__ mask,
                                                    float* __restrict__ out) {
    __shared__ __align__(16) unsigned sWh[2][TJ * D_];
    __shared__ __align__(8) float2 sS2[2][TJ];
    const int bh = blockIdx.y, b = bh >> 2, hh = bh & 3;
    const int tid = threadIdx.x;
    const int warp = tid >> 5, lane = tid & 31;
    const int g  = lane >> 2;
    const int tg = lane & 3;
    const int ib = blockIdx.x * 256;
    const unsigned sbW = (unsigned)__cvta_generic_to_shared(sWh);

    const float m2 = g_m2[bh];
    const bool m2ok = (m2 > -1.0e29f);

    int r0 = ib + warp * 16 + g;
    int rr[4] = { r0, r0 + 8, r0 + 128, r0 + 136 };

    float s1r[4], s1q[4];
    int   mrow[4];
#pragma unroll
    for (int q = 0; q < 4; q++) {
        float s1p = g_s1[bh * N_ + rr[q]];        // prescaled s1*log2e
        float t0 = s1p + m2;
        float rm = fmaxf(t0, NEG_SLOPE * t0);     // rowmax * log2e
        s1r[q] = s1p - rm;
        s1q[q] = fmaf(NEG_SLOPE, s1p, -rm);
        mrow[q] = mask[b * N_ + rr[q]];
    }

    const unsigned* WtB = g_Wt + (size_t)bh * N_ * D_;

#define FILLJ(tile, buf) do {                                              \
        const unsigned* srcW = WtB + (size_t)(tile) * TJ * D_;             \
        _Pragma("unroll")                                                  \
        for (int q = 0; q < 4; q++) {                                      \
            int id = tid + 256 * q;                                        \
            cpa16(sbW + (buf) * SZT + id * 16, srcW + id * 4);             \
        }                                                                  \
        asm volatile("cp.async.commit_group;");                            \
    } while (0)
#define FILLS(tile, buf) do {                                              \
        if (tid < TJ) {                                                    \
            int j = (tile) * TJ + tid;                                     \
            float v = mask[b * N_ + j] ? g_s2[bh * N_ + j] : -1.0e30f;     \
            sS2[buf][tid] = make_float2(v, NEG_SLOPE * v);                 \
        }                                                                  \
    } while (0)

    float acc[2][8][4];
#pragma unroll
    for (int f = 0; f < 2; f++)
#pragma unroll
        for (int nt = 0; nt < 8; nt++)
#pragma unroll
            for (int q = 0; q < 4; q++) acc[f][nt][q] = 0.f;
    float wsum[4] = {0.f, 0.f, 0.f, 0.f};

    FILLJ(0, 0);
    FILLJ(1, 1);
    FILLS(0, 0);
    FILLS(1, 1);

    for (int t = 0; t < N_ / TJ; t++) {
        const int buf = t & 1;
        if (t < N_ / TJ - 1) asm volatile("cp.async.wait_group 1;");
        else                 asm volatile("cp.async.wait_group 0;");
        __syncthreads();

        const unsigned* tile = sWh[buf];
        const float2*   sSt  = sS2[buf];

#pragma unroll 1
        for (int ks = 0; ks < TJ / 8; ks++) {
            const float2 qa = sSt[ks * 8 + tg];
            const float2 qb = sSt[ks * 8 + 4 + tg];

            unsigned af[2][4];
#pragma unroll
            for (int f = 0; f < 2; f++) {
                const int A = f * 2, Bq = f * 2 + 1;
                float w0 = ex2f(fmaxf(s1r[A]  + qa.x, s1q[A]  + qa.y));
                float w1 = ex2f(fmaxf(s1r[Bq] + qa.x, s1q[Bq] + qa.y));
                float w2 = ex2f(fmaxf(s1r[A]  + qb.x, s1q[A]  + qb.y));
                float w3 = ex2f(fmaxf(s1r[Bq] + qb.x, s1q[Bq] + qb.y));
                wsum[A]  += w0 + w2;
                wsum[Bq] += w1 + w3;
                af[f][0] = __float_as_uint(w0) + 0x1000u;  // tf32 round (ALU pipe)
                af[f][1] = __float_as_uint(w1) + 0x1000u;
                af[f][2] = __float_as_uint(w2) + 0x1000u;
                af[f][3] = __float_as_uint(w3) + 0x1000u;
            }

            // B fragments: one LDS.64 per nt gives (k=tg, k=tg+4) pair
            const uint2* bp = (const uint2*)(tile + ks * 512);
            uint2 bf[8];
#pragma unroll
            for (int nt = 0; nt < 8; nt++)
                bf[nt] = bp[(nt * 8 + g) * 4 + tg];

#pragma unroll
            for (int f = 0; f < 2; f++)
#pragma unroll
                for (int nt = 0; nt < 8; nt++) {
                    asm volatile(
                        "mma.sync.aligned.m16n8k8.row.col.f32.tf32.tf32.f32 "
                        "{%0,%1,%2,%3}, {%4,%5,%6,%7}, {%8,%9}, {%0,%1,%2,%3};"
                        : "+f"(acc[f][nt][0]), "+f"(acc[f][nt][1]),
                          "+f"(acc[f][nt][2]), "+f"(acc[f][nt][3])
                        : "r"(af[f][0]), "r"(af[f][1]), "r"(af[f][2]), "r"(af[f][3]),
                          "r"(bf[nt].x), "r"(bf[nt].y));
                }
        }
        __syncthreads();
        if (t + 2 < N_ / TJ) {
            FILLJ(t + 2, buf);
            FILLS(t + 2, buf);
        }
    }

#pragma unroll
    for (int q = 0; q < 4; q++) {
        wsum[q] += __shfl_xor_sync(0xffffffffu, wsum[q], 1);
        wsum[q] += __shfl_xor_sync(0xffffffffu, wsum[q], 2);
    }

#pragma unroll
    for (int q = 0; q < 4; q++) {
        const bool good = mrow[q] && m2ok && (wsum[q] > 0.f);
        const float inv = 1.f / wsum[q];
        const int f = q >> 1;
        const int lohi = (q & 1) * 2;
        float* op = out + ((size_t)(b * N_ + rr[q])) * (H_ * D_) + hh * D_ + tg * 2;
#pragma unroll
        for (int nt = 0; nt < 8; nt++) {
            float2 v;
            v.x = good ? acc[f][nt][lohi + 0] * inv : 0.f;
            v.y = good ? acc[f][nt][lohi + 1] * inv : 0.f;
            *(float2*)(op + nt * 8) = v;
        }
    }
}

// ---------------------------------------------------------------------------
extern "C" void kernel_launch(void* const* d_in, const int* in_sizes, int n_in,
                              void* d_out, int out_size) {
    const float* h    = (const float*)d_in[0];   // [16,1024,256] f32
    const int*   mask = (const int*)  d_in[1];   // [16,1024] i32
    const float* W    = (const float*)d_in[2];   // [256,256] f32
    const float* a    = (const float*)d_in[3];   // [128,1] f32
    float* out = (float*)d_out;                  // [16,1024,256] f32

    int nsplit = (int)((NA4 + NW4 + 255) / 256);
    k_split  <<<nsplit, 256>>>(h, W);
    k_gemm_tc<<<dim3(128, 4), 256>>>(h, W);
    k_scores <<<64, 256>>>(mask, a);
    k_attn_tc<<<dim3(N_ / 256, BH_), 256>>>(mask, out);
}